// round 16
// baseline (speedup 1.0000x reference)
#include <cuda_runtime.h>
#include <cuda_bf16.h>

// Problem dims (fixed by setup_inputs)
#define T_DIM 2048
#define N_DIM 128
#define C_DIM 96
#define NC    (N_DIM * C_DIM)
#define L_DIM 200
#define S_EXT 401            // 2*L+1
#define NWARP 5              // 4 compute + 1 producer
#define NTHR  (NWARP * 32)   // 160
#define KWIN  8              // ticks per window (= barrier period)
#define SPT   4              // states per thread
#define OWNS  112            // owned slots per compute warp (28 threads * 4)
#define HALO  16             // left halo slots (= 2*KWIN = 4 threads)
#define NREC  ((4 * OWNS + HALO) / SPT)   // 116 records
#define NROWF (KWIN * C_DIM) // 768 floats per window buffer
#define LN2   0.69314718055994530942f
#define FIXSCALE 1024.0      // fixed-point scale for deterministic reduction

// Deterministic cross-CTA reduction state (reset by the last CTA each call).
__device__ unsigned long long g_acc  = 0ull;
__device__ unsigned int       g_done = 0u;

// One CTA per batch element. CTC forward, per-thread block-floating-point.
// R16 (= R15 resubmit after infra failure): phases removed from the compute
// warps' serial window:
//  - warp 4 = PRODUCER: all LDG + expf + STS staging (2-window register pipe)
//  - JIT gathers: P values for tick j+2 issued during tick j (no top burst)
//  - register-carry boundary: owners skip the post-barrier reload; only halo
//    lanes (0-3) read SMEM; only lanes 24-31 publish; adoption via shfl.
__global__ __launch_bounds__(NTHR, 1)
void ctc_forward_kernel(const float* __restrict__ predicts,   // (T, N, C)
                        const int*   __restrict__ labels,     // (N, L)
                        const int*   __restrict__ preds_lengths,
                        const int*   __restrict__ label_lengths,
                        float*       __restrict__ out)
{
    const int tid  = threadIdx.x;
    const int n    = blockIdx.x;
    const int w    = tid >> 5;
    const int lane = tid & 31;
    const int sb   = OWNS * w - HALO + SPT * lane;   // first (even) slot
    const bool own = (lane >= HALO / SPT);           // lanes 0..3 are halo
    const int pidx = (sb + HALO) >> 2;               // 28*w + lane

    __shared__ float4 As[2][NREC];    // ping-pong (v0,v1,v2,v3)
    __shared__ int    Ai[2][NREC];    // ping-pong iM
    __shared__ float  Pb[2 * NROWF];  // linear probs, double-buffered
    __shared__ float  FinV[2];
    __shared__ int    FinI[2];

    if (tid < HALO / SPT) {           // permanent zero-pads for slots < 0
        As[0][tid] = make_float4(0.f, 0.f, 0.f, 0.f);
        As[1][tid] = make_float4(0.f, 0.f, 0.f, 0.f);
        Ai[0][tid] = 0; Ai[1][tid] = 0;
    }

    const int len  = preds_lengths[n];
    const int nwin = (len + KWIN - 1) >> 3;   // len uniform per CTA
    const float* gbase = predicts + (size_t)n * C_DIM;

    // Pre-stage rows [0,8) as linear probs into buffer 0 (all threads).
    for (int idx = tid; idx < NROWF; idx += NTHR) {
        const int r = idx / C_DIM, c = idx - r * C_DIM;
        Pb[idx] = __expf(__ldg(gbase + r * NC + c));
    }
    __syncthreads();

    if (w == NWARP - 1) {
        // ================= PRODUCER WARP =================
        // Two 24-float register sets; LDG issued 2 windows before commit.
        float sA[24], sB[24];
#pragma unroll
        for (int rr = 0; rr < 8; ++rr)
#pragma unroll
            for (int g = 0; g < 3; ++g) {
                sA[rr * 3 + g] = __ldg(gbase + (size_t)(1 * KWIN + rr) * NC + lane + 32 * g);
                sB[rr * 3 + g] = __ldg(gbase + (size_t)(2 * KWIN + rr) * NC + lane + 32 * g);
            }
        for (int win = 0; win < nwin; ++win) {
            float* dst = Pb + ((win & 1) ? 0 : NROWF);  // buffer for window win+1
            const int tbase = (win + 3) * KWIN;
            if (!(win & 1)) {
#pragma unroll
                for (int rr = 0; rr < 8; ++rr)
#pragma unroll
                    for (int g = 0; g < 3; ++g) {
                        dst[rr * C_DIM + lane + 32 * g] = __expf(sA[rr * 3 + g]);
                        sA[rr * 3 + g] = (tbase + rr < T_DIM)
                            ? __ldg(gbase + (size_t)(tbase + rr) * NC + lane + 32 * g) : 0.0f;
                    }
            } else {
#pragma unroll
                for (int rr = 0; rr < 8; ++rr)
#pragma unroll
                    for (int g = 0; g < 3; ++g) {
                        dst[rr * C_DIM + lane + 32 * g] = __expf(sB[rr * 3 + g]);
                        sB[rr * 3 + g] = (tbase + rr < T_DIM)
                            ? __ldg(gbase + (size_t)(tbase + rr) * NC + lane + 32 * g) : 0.0f;
                    }
            }
            __syncthreads();   // window boundary (shared with compute warps)
        }
    } else {
        // ================= COMPUTE WARPS =================
        // Odd slots sb+1, sb+3 carry labels; even slots are blanks (no skip).
        int ext1 = 0, ext3 = 0;
        float sk1 = 0.0f, sk3 = 0.0f;
        {
            const int s1 = sb + 1, s3 = sb + 3;
            if (s1 >= 1 && s1 < S_EXT) {
                const int k = s1 >> 1;
                ext1 = labels[n * L_DIM + k];
                if (s1 >= 3) sk1 = (ext1 != labels[n * L_DIM + k - 1]) ? 1.0f : 0.0f;
            }
            if (s3 >= 1 && s3 < S_EXT) {
                const int k = s3 >> 1;
                ext3 = labels[n * L_DIM + k];
                if (s3 >= 3) sk3 = (ext3 != labels[n * L_DIM + k - 1]) ? 1.0f : 0.0f;
            }
        }
        const int end     = 2 * label_lengths[n];
        const int lastwin = (len - 1) >> 3;

        float v0 = (sb == 0) ? 1.0f : 0.0f;   // virtual alpha_{-1}: 1 at slot 0
        float v1 = 0.f, v2 = 0.f, v3 = 0.f;
        int   iM = 0;
        float fp = (lane == 0) ? 0.0f : 1.0f; // all scales equal at t=0

        for (int win = 0; win < nwin; ++win) {
            const float* prow = Pb + ((win & 1) ? NROWF : 0);
            const float u1 = fp * sk1;
            const bool isLast = (win == lastwin);

            // JIT gather pipeline: prologue loads ticks 0 and 1.
            float a0 = prow[0],         a1 = prow[ext1],         a3 = prow[ext3];
            float b0 = prow[C_DIM],     b1 = prow[C_DIM + ext1], b3 = prow[C_DIM + ext3];

#pragma unroll
            for (int j = 0; j < KWIN; ++j) {
                const float g0 = a0, g1 = a1, g3 = a3;
                a0 = b0; a1 = b1; a3 = b3;
                if (j + 2 < KWIN) {                 // issue loads for tick j+2
                    const float* r = prow + (j + 2) * C_DIM;
                    b0 = r[0]; b1 = r[ext1]; b3 = r[ext3];
                }
                const float c1 = u1 * g1;           // chain coeffs (off-chain)
                const float c3 = sk3 * g3;

                const float vp  = __shfl_up_sync(0xffffffffu, v3, 1);
                const float nv0 = __fmaf_rn(vp, fp, v0) * g0;
                const float nv1 = __fmaf_rn(vp, c1, (v1 + v0) * g1);
                const float nv2 = (v2 + v1) * g0;
                const float nv3 = __fmaf_rn(v1, c3, (v3 + v2) * g3);
                v0 = nv0; v1 = nv1; v2 = nv2; v3 = nv3;

                if (isLast) {
                    const int t = (win << 3) + j;
                    if (t == len - 1 && own) {      // record final states
                        if (sb == end)         { FinV[0] = v0; FinI[0] = iM; }
                        if (sb + 2 == end)     { FinV[0] = v2; FinI[0] = iM; }
                        if (sb + 1 == end - 1) { FinV[1] = v1; FinI[1] = iM; }
                        if (sb + 3 == end - 1) { FinV[1] = v3; FinI[1] = iM; }
                    }
                }
            }

            // ---- window boundary ----
            // 1) per-thread renorm.
            const float mx = fmaxf(fmaxf(v0, v1), fmaxf(v2, v3));
            if (mx > 0.0f) {
                const int e = (int)(__float_as_uint(mx) >> 23) - 127;
                iM += e;
                const float sc = __int_as_float((unsigned)(127 - e) << 23);
                v0 *= sc; v1 *= sc; v2 *= sc; v3 *= sc;
            }
            // 2) only lanes 24..31 are read cross-warp -> only they publish.
            const int ab = win & 1;
            if (lane >= 24) {
                As[ab][pidx] = make_float4(v0, v1, v2, v3);
                Ai[ab][pidx] = iM;
            }
            __syncthreads();
            // 3) halo lanes (0..3) reload from the left warp; owners carry regs.
            int iMaL = 0;
            if (lane < 4) {
                const float4 pv = As[ab][pidx];
                v0 = pv.x; v1 = pv.y; v2 = pv.z; v3 = pv.w;
                iM = Ai[ab][pidx];
                iMaL = Ai[ab][(pidx >= 4) ? (pidx - 4) : 0];  // adoption source
            }
            // 4) adoption: lanes>=4 source via shfl (pre-adoption iM), halo via SMEM.
            const int iMs = __shfl_up_sync(0xffffffffu, iM, 4);
            const int iMa = (lane < 4) ? iMaL : iMs;
            iM = (fmaxf(fmaxf(v0, v1), fmaxf(v2, v3)) == 0.0f) ? iMa : iM;

            // 5) fixed per-window neighbor rescale from post-adoption scales.
            const int iMp = __shfl_up_sync(0xffffffffu, iM, 1);
            int k = iMp - iM;
            k = (k > 125) ? 125 : ((k < -127) ? -127 : k);
            fp = __int_as_float((unsigned)(k + 127) << 23);  // k=-127 -> exact 0
            if (lane == 0) fp = 0.0f;
        }
    }

    __syncthreads();
    if (tid == 0) {
        const float f0 = __log2f(FinV[0]) + (float)FinI[0];
        const float f1 = __log2f(FinV[1]) + (float)FinI[1];
        const float mm   = fmaxf(f0, f1);
        const float fin2 = mm + __log2f(exp2f(f0 - mm) + exp2f(f1 - mm));
        const float ctc  = -(fin2 * LN2);
        const float fw   = 1.0f - __expf(-ctc);     // focal: alpha=1, gamma=2
        const double contrib = (double)(ctc * (fw * fw));

        // Deterministic reduction: integer fixed-point atomic (exactly
        // associative), last CTA converts + writes + resets for next replay.
        const unsigned long long q =
            (unsigned long long)(long long)(contrib * FIXSCALE + 0.5);
        atomicAdd(&g_acc, q);
        __threadfence();
        const unsigned rank = atomicAdd(&g_done, 1u);
        if (rank == N_DIM - 1) {
            const unsigned long long total = atomicAdd(&g_acc, 0ull);
            out[0] = (float)((double)total / FIXSCALE);
            g_acc  = 0ull;          // reset for the next graph replay
            g_done = 0u;
        }
    }
}

extern "C" void kernel_launch(void* const* d_in, const int* in_sizes, int n_in,
                              void* d_out, int out_size)
{
    const float* predicts      = (const float*)d_in[0];
    const int*   labels        = (const int*)  d_in[1];
    // d_in[2] = ref_labels (unused), d_in[5] = ref_length (unused)
    const int*   preds_lengths = (const int*)  d_in[3];
    const int*   label_lengths = (const int*)  d_in[4];
    float*       out           = (float*)d_out;

    ctc_forward_kernel<<<N_DIM, NTHR>>>(predicts, labels, preds_lengths,
                                        label_lengths, out);
}

// round 17
// speedup vs baseline: 1.0551x; 1.0551x over previous
#include <cuda_runtime.h>
#include <cuda_bf16.h>

// Problem dims (fixed by setup_inputs)
#define T_DIM 2048
#define N_DIM 128
#define C_DIM 96
#define NC    (N_DIM * C_DIM)
#define L_DIM 200
#define S_EXT 401            // 2*L+1
#define NWARP 4
#define NTHR  (NWARP * 32)   // 128
#define KWIN  8              // ticks per window (= barrier period)
#define NCMP  4              // composite (2-tick) steps per window
#define SPT   4              // states per thread
#define OWNS  112            // owned slots per warp (28 threads * 4)
#define HALO  16             // left halo slots per warp (= 2*KWIN = 4 threads)
#define NREC  ((NWARP * OWNS + HALO) / SPT)   // 116 records
#define LN2   0.69314718055994530942f
#define FIXSCALE 1024.0      // fixed-point scale for deterministic reduction

// Deterministic cross-CTA reduction state (reset by the last CTA each call).
__device__ unsigned long long g_acc  = 0ull;
__device__ unsigned int       g_done = 0u;

// One CTA per batch element. CTC forward, per-thread block-floating-point
// (4 adjacent states per thread, linear floats + power-of-two scale iM).
// R17 = R13 skeleton + COMPOSITE 2-TICK STEPS: one shuffle of the left
// thread's (v1,v2,v3) serves two time steps -- the left's intermediate v3
// is recomputed locally from the shuffled triple using the left slot's
// label prob (extra gather PL) and skip flag. Serial steps: 2048 -> 1024.
// Last window runs tick-by-tick to record t == len-1 exactly.
__global__ __launch_bounds__(NTHR, 1)
void ctc_forward_kernel(const float* __restrict__ predicts,   // (T, N, C)
                        const int*   __restrict__ labels,     // (N, L)
                        const int*   __restrict__ preds_lengths,
                        const int*   __restrict__ label_lengths,
                        float*       __restrict__ out)
{
    const int tid  = threadIdx.x;
    const int n    = blockIdx.x;
    const int w    = tid >> 5;
    const int lane = tid & 31;
    const int sb   = OWNS * w - HALO + SPT * lane;   // first (even) slot
    const bool own = (lane >= HALO / SPT);           // lanes 0..3 are halo
    const int pidx = (sb + HALO) >> 2;               // 28*w + lane

    __shared__ float4 As[2][NREC];    // ping-pong (v0,v1,v2,v3)
    __shared__ int    Ai[2][NREC];    // ping-pong iM
    __shared__ float  Pb[2 * KWIN * C_DIM];  // linear probs, double-buffered
    __shared__ float  FinV[2];
    __shared__ int    FinI[2];

    if (tid < HALO / SPT) {           // permanent zero-pads for slots < 0
        As[0][tid] = make_float4(0.f, 0.f, 0.f, 0.f);
        As[1][tid] = make_float4(0.f, 0.f, 0.f, 0.f);
        Ai[0][tid] = 0; Ai[1][tid] = 0;
    }

    // Odd slots sb+1, sb+3 carry labels; even are blanks. extL/skL describe
    // the LEFT thread's top slot sb-1 (for the composite's local recompute).
    int ext1 = 0, ext3 = 0, extL = 0;
    float sk1 = 0.0f, sk3 = 0.0f, skL = 0.0f;
    {
        const int s1 = sb + 1, s3 = sb + 3, sl = sb - 1;
        if (s1 >= 1 && s1 < S_EXT) {
            const int k = s1 >> 1;
            ext1 = labels[n * L_DIM + k];
            if (s1 >= 3) sk1 = (ext1 != labels[n * L_DIM + k - 1]) ? 1.0f : 0.0f;
        }
        if (s3 >= 1 && s3 < S_EXT) {
            const int k = s3 >> 1;
            ext3 = labels[n * L_DIM + k];
            if (s3 >= 3) sk3 = (ext3 != labels[n * L_DIM + k - 1]) ? 1.0f : 0.0f;
        }
        if (sl >= 1 && sl < S_EXT) {
            const int k = sl >> 1;
            extL = labels[n * L_DIM + k];
            if (sl >= 3) skL = (extL != labels[n * L_DIM + k - 1]) ? 1.0f : 0.0f;
        }
    }
    const int len     = preds_lengths[n];
    const int end     = 2 * label_lengths[n];
    const int lastwin = (len - 1) >> 3;

    // Cooperative staging geometry: 8 rows x 96 classes = 768 floats, 6/thread.
    const float* gbase = predicts + (size_t)n * C_DIM;
    int off_q[6], r_q[6];
#pragma unroll
    for (int q = 0; q < 6; ++q) {
        const int idx = tid + q * NTHR;
        const int r = idx / C_DIM, c = idx - r * C_DIM;
        r_q[q]   = r;
        off_q[q] = r * NC + c;
    }

    // Pre-stage rows [0,8) into buffer 0; prime the depth-3 register pipeline.
    float stgA[6], stgB[6], stgC[6];
#pragma unroll
    for (int q = 0; q < 6; ++q) {
        Pb[tid + q * NTHR] = __expf(__ldg(gbase + off_q[q]));
        stgA[q] = __ldg(gbase + off_q[q] + (size_t)(1 * KWIN) * NC);
        stgB[q] = __ldg(gbase + off_q[q] + (size_t)(2 * KWIN) * NC);
        stgC[q] = __ldg(gbase + off_q[q] + (size_t)(3 * KWIN) * NC);
    }
    __syncthreads();

    float v0 = (sb == 0) ? 1.0f : 0.0f;   // virtual alpha_{-1}: 1 at slot 0
    float v1 = 0.f, v2 = 0.f, v3 = 0.f;
    int   iM = 0;
    float fp = (lane == 0) ? 0.0f : 1.0f; // all scales equal at t=0
    const int nwin = (len + KWIN - 1) >> 3;   // len uniform per CTA

    for (int win = 0; win < nwin; ++win) {
        // --- window top: gather P values for 4 composite (2-tick) steps ---
        const float* prow = Pb + ((win & 1) ? KWIN * C_DIM : 0);
        float P0[NCMP], P1[NCMP], P3[NCMP], PL[NCMP];  // even ticks (step A)
        float Q0[NCMP], Q1[NCMP], Q3[NCMP];            // odd ticks (step B)
#pragma unroll
        for (int c = 0; c < NCMP; ++c) {
            const float* rA = prow + (2 * c) * C_DIM;
            const float* rB = prow + (2 * c + 1) * C_DIM;
            P0[c] = rA[0];  P1[c] = rA[ext1];  P3[c] = rA[ext3];  PL[c] = rA[extL];
            Q0[c] = rB[0];  Q1[c] = rB[ext1];  Q3[c] = rB[ext3];
        }

        // --- commit next window's rows into the OTHER buffer, then refill ---
        {
            float* dst = Pb + ((win & 1) ? 0 : KWIN * C_DIM);
            const int tnext = (win + 4) * KWIN;
            const int set   = win % 3;
            if (set == 0) {
#pragma unroll
                for (int q = 0; q < 6; ++q) {
                    dst[tid + q * NTHR] = __expf(stgA[q]);
                    stgA[q] = (tnext + r_q[q] < T_DIM)
                              ? __ldg(gbase + off_q[q] + (size_t)tnext * NC) : 0.0f;
                }
            } else if (set == 1) {
#pragma unroll
                for (int q = 0; q < 6; ++q) {
                    dst[tid + q * NTHR] = __expf(stgB[q]);
                    stgB[q] = (tnext + r_q[q] < T_DIM)
                              ? __ldg(gbase + off_q[q] + (size_t)tnext * NC) : 0.0f;
                }
            } else {
#pragma unroll
                for (int q = 0; q < 6; ++q) {
                    dst[tid + q * NTHR] = __expf(stgC[q]);
                    stgC[q] = (tnext + r_q[q] < T_DIM)
                              ? __ldg(gbase + off_q[q] + (size_t)tnext * NC) : 0.0f;
                }
            }
        }

        if (win != lastwin) {
            // --- composite loop: 4 x (2 ticks per 1 shuffle-exchange) ---
#pragma unroll
            for (int c = 0; c < NCMP; ++c) {
                const float v1L = __shfl_up_sync(0xffffffffu, v1, 1);
                const float v2L = __shfl_up_sync(0xffffffffu, v2, 1);
                const float v3L = __shfl_up_sync(0xffffffffu, v3, 1);

                // left's step-A v3 (recomputed locally; fp masks lane 0)
                const float v3pL = (v3L + v2L + v1L * skL) * PL[c];

                // step A (tick 2c)
                const float m1 = fp * v3L;
                const float t0 = (v0 + m1) * P0[c];
                const float t1 = (v1 + v0 + m1 * sk1) * P1[c];
                const float t2 = (v2 + v1) * P0[c];
                const float t3 = (v3 + v2 + v1 * sk3) * P3[c];

                // step B (tick 2c+1)
                const float m2 = fp * v3pL;
                v0 = (t0 + m2) * Q0[c];
                v1 = (t1 + t0 + m2 * sk1) * Q1[c];
                v2 = (t2 + t1) * Q0[c];
                v3 = (t3 + t2 + t1 * sk3) * Q3[c];
            }
        } else {
            // --- last window: plain tick loop to hit t == len-1 exactly ---
#pragma unroll
            for (int j = 0; j < KWIN; ++j) {
                const int c  = j >> 1;
                const float g0 = (j & 1) ? Q0[c] : P0[c];
                const float g1 = (j & 1) ? Q1[c] : P1[c];
                const float g3 = (j & 1) ? Q3[c] : P3[c];

                const float vp  = __shfl_up_sync(0xffffffffu, v3, 1) * fp;
                const float nv0 = (v0 + vp) * g0;
                const float nv1 = (v1 + v0 + vp * sk1) * g1;
                const float nv2 = (v2 + v1) * g0;
                const float nv3 = (v3 + v2 + v1 * sk3) * g3;
                v0 = nv0; v1 = nv1; v2 = nv2; v3 = nv3;

                const int t = (win << 3) + j;
                if (t == len - 1 && own) {       // record final states
                    if (sb == end)         { FinV[0] = v0; FinI[0] = iM; }
                    if (sb + 2 == end)     { FinV[0] = v2; FinI[0] = iM; }
                    if (sb + 1 == end - 1) { FinV[1] = v1; FinI[1] = iM; }
                    if (sb + 3 == end - 1) { FinV[1] = v3; FinI[1] = iM; }
                }
            }
        }

        // ---- window boundary (identical to R13) ----
        const float mx = fmaxf(fmaxf(v0, v1), fmaxf(v2, v3));
        if (mx > 0.0f) {
            const int e = (int)(__float_as_uint(mx) >> 23) - 127;
            iM += e;
            const float sc = __int_as_float((unsigned)(127 - e) << 23);
            v0 *= sc; v1 *= sc; v2 *= sc; v3 *= sc;
        }
        const int ab = win & 1;
        if (own) {
            As[ab][pidx] = make_float4(v0, v1, v2, v3);
            Ai[ab][pidx] = iM;
        }
        __syncthreads();
        const float4 pv  = As[ab][pidx];
        const int    iMr = Ai[ab][pidx];
        const int    iMa = Ai[ab][(pidx >= 4) ? (pidx - 4) : 0];  // parallel load
        v0 = pv.x; v1 = pv.y; v2 = pv.z; v3 = pv.w;
        iM = (fmaxf(fmaxf(v0, v1), fmaxf(v2, v3)) == 0.0f) ? iMa : iMr;

        const int iMp = __shfl_up_sync(0xffffffffu, iM, 1);
        int k = iMp - iM;
        k = (k > 125) ? 125 : ((k < -127) ? -127 : k);
        fp = __int_as_float((unsigned)(k + 127) << 23);  // k=-127 -> exact 0
        if (lane == 0) fp = 0.0f;
    }

    __syncthreads();
    if (tid == 0) {
        const float f0 = __log2f(FinV[0]) + (float)FinI[0];
        const float f1 = __log2f(FinV[1]) + (float)FinI[1];
        const float mm   = fmaxf(f0, f1);
        const float fin2 = mm + __log2f(exp2f(f0 - mm) + exp2f(f1 - mm));
        const float ctc  = -(fin2 * LN2);
        const float fw   = 1.0f - __expf(-ctc);     // focal: alpha=1, gamma=2
        const double contrib = (double)(ctc * (fw * fw));

        // Deterministic reduction: integer fixed-point atomic (exactly
        // associative), last CTA converts + writes + resets for next replay.
        const unsigned long long q =
            (unsigned long long)(long long)(contrib * FIXSCALE + 0.5);
        atomicAdd(&g_acc, q);
        __threadfence();
        const unsigned rank = atomicAdd(&g_done, 1u);
        if (rank == N_DIM - 1) {
            const unsigned long long total = atomicAdd(&g_acc, 0ull);
            out[0] = (float)((double)total / FIXSCALE);
            g_acc  = 0ull;          // reset for the next graph replay
            g_done = 0u;
        }
    }
}

extern "C" void kernel_launch(void* const* d_in, const int* in_sizes, int n_in,
                              void* d_out, int out_size)
{
    const float* predicts      = (const float*)d_in[0];
    const int*   labels        = (const int*)  d_in[1];
    // d_in[2] = ref_labels (unused), d_in[5] = ref_length (unused)
    const int*   preds_lengths = (const int*)  d_in[3];
    const int*   label_lengths = (const int*)  d_in[4];
    float*       out           = (float*)d_out;

    ctc_forward_kernel<<<N_DIM, NTHR>>>(predicts, labels, preds_lengths,
                                        label_lengths, out);
}